// round 3
// baseline (speedup 1.0000x reference)
#include <cuda_runtime.h>
#include <math.h>

// Problem constants
#define BB 8
#define CC 256
#define HH 128
#define WW 128
#define HP 64
#define WP 64
#define NC8 32
#define CE  240   // enhanced output channels of fused conv
#define FIN 496   // fused conv input channels (240 bev + 256 T)

// -------- scratch (device globals; no allocation allowed) --------
__device__ float g_A[3][BB][CC][WW];          // A0=S-x_bot, A1=S, A2=S-x_top
__device__ float g_bevpool[BB][CC][HP][WP];   // avgpool2(bev_x)
__device__ float g_k[BB][NC8][WP];
__device__ float g_kq[BB][CC][WP];
__device__ float g_kqb[BB][WP];
__device__ float g_e[BB][HP][WP];             // energy, then normalized in-place
__device__ float g_vs[BB][CC][WP];            // vsum
__device__ float g_G[BB][CE][9][WP];          // fw2 (x) vs

// ---------------------------------------------------------------
// K1: column sums of front_x + first/last row corrections
// grid (CC, BB), block 128 (w)
__global__ void front_reduce_kernel(const float* __restrict__ fx) {
    int c = blockIdx.x, b = blockIdx.y, w = threadIdx.x;
    const float* p = fx + (((size_t)b * CC + c) * HH) * WW + w;
    float x0 = p[0];
    float xN = p[127 * WW];
    float s = 0.f;
#pragma unroll 8
    for (int h = 0; h < HH; h++) s += p[h * WW];
    g_A[0][b][c][w] = s - xN;   // pairs with weight row dy=0
    g_A[1][b][c][w] = s;        // dy=1
    g_A[2][b][c][w] = s - x0;   // dy=2
}

// K2: 2x2 avgpool of bev_x   (one thread per pooled element)
__global__ void bevpool_kernel(const float* __restrict__ bev) {
    int idx = blockIdx.x * 256 + threadIdx.x;  // BB*CC*HP*WP = 8388608
    int w  = idx & 63;
    int h  = (idx >> 6) & 63;
    int bc = idx >> 12;
    const float2* r0 = (const float2*)(bev + ((size_t)bc * HH + 2 * h) * WW);
    const float2* r1 = (const float2*)(bev + ((size_t)bc * HH + 2 * h + 1) * WW);
    float2 a = r0[w], d = r1[w];
    ((float*)g_bevpool)[idx] = 0.25f * (a.x + a.y + d.x + d.y);
}

// K3: k[b,o,w'] = sum_c kw[o,c]*mean_h_pooled(front) + kb
__global__ void k_kernel(const float* __restrict__ kw, const float* __restrict__ kb) {
    int tid = blockIdx.x * 256 + threadIdx.x;  // 8*32*64 = 16384
    int w = tid & 63, o = (tid >> 6) & 31, b = tid >> 11;
    float acc = 0.f;
#pragma unroll 4
    for (int c = 0; c < CC; c++) {
        float m = (g_A[1][b][c][2 * w] + g_A[1][b][c][2 * w + 1]) * (1.f / 256.f);
        acc += kw[o * CC + c] * m;
    }
    g_k[b][o][w] = acc + kb[o];
}

// K4: kq[b,c,w'] = sum_o k[b,o,w']*qw[o,c]; kqb[b,w'] = sum_o k*qb
__global__ void kq_kernel(const float* __restrict__ qw, const float* __restrict__ qb) {
    int tid = blockIdx.x * 256 + threadIdx.x;  // 8*256*64 = 131072
    int w = tid & 63, c = (tid >> 6) & 255, b = tid >> 14;
    float acc = 0.f, accb = 0.f;
#pragma unroll 8
    for (int o = 0; o < NC8; o++) {
        float kk = g_k[b][o][w];
        acc  += kk * qw[o * CC + c];
        accb += kk * qb[o];
    }
    g_kq[b][c][w] = acc;
    if (c == 0) g_kqb[b][w] = accb;
}

// K5: e[b,h',w'] = kqb + sum_c kq[b,c,w']*bevpool[b,c,h',w']
// grid (HP, BB), block WP
__global__ void e_kernel() {
    int w = threadIdx.x, h = blockIdx.x, b = blockIdx.y;
    float acc = g_kqb[b][w];
#pragma unroll 4
    for (int c = 0; c < CC; c++)
        acc += g_kq[b][c][w] * g_bevpool[b][c][h][w];
    g_e[b][h][w] = acc;
}

// K6: L2-normalize e over h' per (b, w').  grid (WP, BB), block HP
__global__ void enorm_kernel() {
    int w = blockIdx.x, b = blockIdx.y, h = threadIdx.x;
    float v = g_e[b][h][w];
    float s = v * v;
#pragma unroll
    for (int off = 16; off; off >>= 1) s += __shfl_xor_sync(0xffffffffu, s, off);
    __shared__ float sh[2];
    if ((h & 31) == 0) sh[h >> 5] = s;
    __syncthreads();
    float tot = sh[0] + sh[1];
    g_e[b][h][w] = v * rsqrtf(tot);
}

// K7: vsum via 3-tap 1D conv on A rows.  grid (32 c-groups, BB), block 64 (w')
__global__ void vsum_kernel(const float* __restrict__ vw, const float* __restrict__ vb) {
    __shared__ float sA[3][132];   // index u = wf+dx in [0,129]; 0/129 are zero pad
    __shared__ float sW[8][9];
    int b = blockIdx.y, cg = blockIdx.x;
    int t = threadIdx.x;
    float acc[8];
#pragma unroll
    for (int j = 0; j < 8; j++) acc[j] = 0.f;

    for (int ci = 0; ci < CC; ci++) {
        __syncthreads();
        for (int i = t; i < 3 * 130; i += 64) {
            int arr = i / 130, u = i % 130;
            float v = 0.f;
            if (u >= 1 && u <= 128) v = g_A[arr][b][ci][u - 1];
            sA[arr][u] = v;
        }
        // FIX (R1): block has 64 threads; must loop to cover all 72 weights.
        for (int i = t; i < 72; i += 64) {
            int j = i / 9, kk = i % 9;
            sW[j][kk] = vw[((size_t)(cg * 8 + j) * CC + ci) * 9 + kk];
        }
        __syncthreads();
#pragma unroll
        for (int sub = 0; sub < 2; sub++) {
            int wf = 2 * t + sub;
            float a[3][3];
#pragma unroll
            for (int dy = 0; dy < 3; dy++)
#pragma unroll
                for (int dx = 0; dx < 3; dx++) a[dy][dx] = sA[dy][wf + dx];
#pragma unroll
            for (int j = 0; j < 8; j++) {
                float s = acc[j];
#pragma unroll
                for (int dy = 0; dy < 3; dy++)
#pragma unroll
                    for (int dx = 0; dx < 3; dx++) s += sW[j][dy * 3 + dx] * a[dy][dx];
                acc[j] = s;
            }
        }
    }
#pragma unroll
    for (int j = 0; j < 8; j++)
        g_vs[b][cg * 8 + j][t] = 0.25f * acc[j] + 64.f * vb[cg * 8 + j];
}

// K8: G[b,o,k,w'] = sum_c fw[o,240+c,k]*vs[b,c,w'].  grid (CE, BB), block 64
__global__ void G_kernel(const float* __restrict__ fw) {
    int b = blockIdx.y, o = blockIdx.x, t = threadIdx.x;
    float acc[9];
#pragma unroll
    for (int j = 0; j < 9; j++) acc[j] = 0.f;
    for (int c = 0; c < CC; c++) {
        float v = g_vs[b][c][t];
        const float* wp = fw + ((size_t)o * FIN + 240 + c) * 9;
#pragma unroll
        for (int j = 0; j < 9; j++) acc[j] += wp[j] * v;
    }
#pragma unroll
    for (int j = 0; j < 9; j++) g_G[b][o][j][t] = acc[j];
}

// K9: passthrough of first 16 channels (float4 copy)
__global__ void copy16_kernel(const float* __restrict__ bev, float* __restrict__ out) {
    int idx = blockIdx.x * 256 + threadIdx.x;  // 8*16*16384/4 = 524288
    int b = idx / (16 * 4096);
    int r = idx - b * (16 * 4096);
    size_t off = (size_t)b * (CC * 4096) + r;
    ((float4*)out)[off] = ((const float4*)bev)[off];
}

// K10: fused 3x3 conv on bev_x[:,16:] + T-part epilogue + bias.
// Block: 16 out-ch x 16x16 px. Thread: 4 out-ch x 2x2 px.
// Input channels processed 4 per sync phase (60 phases total).
// grid (64 xy-tiles, 15 o-tiles, BB), block 256
#define CIB 4
__global__ void __launch_bounds__(256)
fused_conv_kernel(const float* __restrict__ bev, const float* __restrict__ fw,
                  const float* __restrict__ fb, float* __restrict__ out) {
    __shared__ float s_in[CIB][18][20];
    __shared__ float s_w[CIB][16][9];

    int b  = blockIdx.z;
    int ot = blockIdx.y;                 // 0..14
    int xt = blockIdx.x & 7, yt = blockIdx.x >> 3;
    int x0 = xt * 16, y0 = yt * 16;

    int t  = threadIdx.x;
    int og = t >> 6;                     // 0..3
    int r  = t & 63;
    int py = r >> 3, px = r & 7;
    int yb = 2 * py, xb = 2 * px;        // thread pixel base inside tile

    float acc[4][4];
#pragma unroll
    for (int i = 0; i < 4; i++)
#pragma unroll
        for (int j = 0; j < 4; j++) acc[i][j] = 0.f;

    const float* bevb = bev + (size_t)b * CC * (HH * WW);

    for (int cb = 0; cb < 240; cb += CIB) {
        __syncthreads();
        // load CIB input planes (halo tiles 18x18) into smem
        for (int i = t; i < CIB * 18 * 18; i += 256) {
            int ci4 = i / 324;
            int rem = i - ci4 * 324;
            int iy = rem / 18, ix = rem - iy * 18;
            int gy = y0 + iy - 1, gx = x0 + ix - 1;
            float v = 0.f;
            if ((unsigned)gy < 128u && (unsigned)gx < 128u)
                v = bevb[(size_t)(16 + cb + ci4) * (HH * WW) + gy * WW + gx];
            s_in[ci4][iy][ix] = v;
        }
        // load CIB x 16 x 9 weights
        for (int i = t; i < CIB * 144; i += 256) {
            int ci4 = i / 144;
            int rr = i - ci4 * 144;
            int ow = rr / 9, kk = rr - ow * 9;
            s_w[ci4][ow][kk] = fw[((size_t)(ot * 16 + ow) * FIN + cb + ci4) * 9 + kk];
        }
        __syncthreads();

#pragma unroll
        for (int ci4 = 0; ci4 < CIB; ci4++) {
            float in[4][4];
#pragma unroll
            for (int iy = 0; iy < 4; iy++)
#pragma unroll
                for (int ix = 0; ix < 4; ix++) in[iy][ix] = s_in[ci4][yb + iy][xb + ix];

#pragma unroll
            for (int oi = 0; oi < 4; oi++) {
                const float* w = s_w[ci4][og * 4 + oi];
                float w0 = w[0], w1 = w[1], w2 = w[2];
                float w3 = w[3], w4 = w[4], w5 = w[5];
                float w6 = w[6], w7 = w[7], w8 = w[8];
#pragma unroll
                for (int sy = 0; sy < 2; sy++)
#pragma unroll
                    for (int sx = 0; sx < 2; sx++) {
                        float a = acc[oi][sy * 2 + sx];
                        a += w0 * in[sy + 0][sx + 0];
                        a += w1 * in[sy + 0][sx + 1];
                        a += w2 * in[sy + 0][sx + 2];
                        a += w3 * in[sy + 1][sx + 0];
                        a += w4 * in[sy + 1][sx + 1];
                        a += w5 * in[sy + 1][sx + 2];
                        a += w6 * in[sy + 2][sx + 0];
                        a += w7 * in[sy + 2][sx + 1];
                        a += w8 * in[sy + 2][sx + 2];
                        acc[oi][sy * 2 + sx] = a;
                    }
            }
        }
    }

    // Epilogue: bias + factorized T contribution, then store
#pragma unroll
    for (int oi = 0; oi < 4; oi++) {
        int o = ot * 16 + og * 4 + oi;
        float bias = fb[o];
#pragma unroll
        for (int sy = 0; sy < 2; sy++)
#pragma unroll
            for (int sx = 0; sx < 2; sx++) {
                int y = y0 + yb + sy, x = x0 + xb + sx;
                float v = acc[oi][sy * 2 + sx] + bias;
#pragma unroll
                for (int dy = 0; dy < 3; dy++) {
                    int yy = y + dy - 1;
                    if ((unsigned)yy >= 128u) continue;
                    int hh = yy >> 1;
#pragma unroll
                    for (int dx = 0; dx < 3; dx++) {
                        int xx = x + dx - 1;
                        if ((unsigned)xx >= 128u) continue;
                        int ww = xx >> 1;
                        v += g_e[b][hh][ww] * g_G[b][o][dy * 3 + dx][ww];
                    }
                }
                out[((size_t)(b * CC + 16 + o) * HH + y) * WW + x] = v;
            }
    }
}

// ---------------------------------------------------------------
extern "C" void kernel_launch(void* const* d_in, const int* in_sizes, int n_in,
                              void* d_out, int out_size) {
    const float* front = (const float*)d_in[0];
    const float* bev   = (const float*)d_in[1];
    const float* qw    = (const float*)d_in[2];
    const float* qb    = (const float*)d_in[3];
    const float* kw    = (const float*)d_in[4];
    const float* kb    = (const float*)d_in[5];
    const float* vw    = (const float*)d_in[6];
    const float* vb    = (const float*)d_in[7];
    const float* fw    = (const float*)d_in[8];
    const float* fb    = (const float*)d_in[9];
    float* out = (float*)d_out;

    front_reduce_kernel<<<dim3(CC, BB), 128>>>(front);
    bevpool_kernel<<<(BB * CC * HP * WP) / 256, 256>>>(bev);
    k_kernel<<<64, 256>>>(kw, kb);
    kq_kernel<<<512, 256>>>(qw, qb);
    e_kernel<<<dim3(HP, BB), WP>>>();
    enorm_kernel<<<dim3(WP, BB), HP>>>();
    vsum_kernel<<<dim3(32, BB), 64>>>(vw, vb);
    G_kernel<<<dim3(CE, BB), 64>>>(fw);
    copy16_kernel<<<2048, 256>>>(bev, out);
    fused_conv_kernel<<<dim3(64, 15, BB), 256>>>(bev, fw, fb, out);
}